// round 5
// baseline (speedup 1.0000x reference)
#include <cuda_runtime.h>

// hidden [4096] f32, encoder_outputs [8192,1,4096] f32
// energies = enc @ hidden -> softmax -> output = enc^T @ attn
// d_out: [0:4096) = output, [4096:12288) = attn
//
// Single-pass: enc is read ONCE. Each block does online-softmax accumulation
// of its 32 rows into a register-resident 4096-wide partial, spilled to
// scratch; a combine kernel merges 256 partials + writes attn.

#define SEQ_LEN 8192
#define HIDDEN  4096
#define H4      (HIDDEN / 4)
#define NBLK    256
#define ROWS_A  (SEQ_LEN / NBLK)   // 32 rows per block

__device__ float g_energies[SEQ_LEN];
__device__ float g_partial[NBLK * HIDDEN];
__device__ float g_m[NBLK];
__device__ float g_l[NBLK];

// ---- Pass 1: fused energies + online-softmax weighted accumulation --------
__global__ __launch_bounds__(256) void pass1(
    const float* __restrict__ enc, const float* __restrict__ hidden)
{
    const int tid  = threadIdx.x;
    const int wid  = tid >> 5;
    const int lane = tid & 31;
    const int r0   = blockIdx.x * ROWS_A;

    __shared__ float sm[2][8];

    const float4* h4 = reinterpret_cast<const float4*>(hidden);
    // thread-owned hidden slice (float4 indices tid, tid+256, tid+512, tid+768)
    float4 hv0 = h4[tid];
    float4 hv1 = h4[tid + 256];
    float4 hv2 = h4[tid + 512];
    float4 hv3 = h4[tid + 768];

    const float4* base = reinterpret_cast<const float4*>(enc + (size_t)r0 * HIDDEN);

    // current row slice
    float4 c0 = base[tid];
    float4 c1 = base[tid + 256];
    float4 c2 = base[tid + 512];
    float4 c3 = base[tid + 768];

    float4 a0 = make_float4(0.f,0.f,0.f,0.f);
    float4 a1 = a0, a2 = a0, a3 = a0;
    float m = -3.4e38f;
    float l = 0.f;

    #pragma unroll 1
    for (int s = 0; s < ROWS_A; ++s) {
        // prefetch next row (clamped; last iteration reloads same row, harmless)
        int sn = (s + 1 < ROWS_A) ? s + 1 : s;
        const float4* nb = base + (size_t)sn * H4;
        float4 n0 = nb[tid];
        float4 n1 = nb[tid + 256];
        float4 n2 = nb[tid + 512];
        float4 n3 = nb[tid + 768];

        // energy dot for current row
        float part = c0.x*hv0.x + c0.y*hv0.y + c0.z*hv0.z + c0.w*hv0.w
                   + c1.x*hv1.x + c1.y*hv1.y + c1.z*hv1.z + c1.w*hv1.w
                   + c2.x*hv2.x + c2.y*hv2.y + c2.z*hv2.z + c2.w*hv2.w
                   + c3.x*hv3.x + c3.y*hv3.y + c3.z*hv3.z + c3.w*hv3.w;
        #pragma unroll
        for (int off = 16; off > 0; off >>= 1)
            part += __shfl_down_sync(0xFFFFFFFFu, part, off);
        if (lane == 0) sm[s & 1][wid] = part;
        __syncthreads();
        float e = sm[s & 1][0] + sm[s & 1][1] + sm[s & 1][2] + sm[s & 1][3]
                + sm[s & 1][4] + sm[s & 1][5] + sm[s & 1][6] + sm[s & 1][7];
        if (tid == 0) g_energies[r0 + s] = e;

        // online softmax update
        float mn = fmaxf(m, e);
        float sc = __expf(m - mn);
        float p  = __expf(e - mn);
        a0.x = a0.x*sc + p*c0.x;  a0.y = a0.y*sc + p*c0.y;
        a0.z = a0.z*sc + p*c0.z;  a0.w = a0.w*sc + p*c0.w;
        a1.x = a1.x*sc + p*c1.x;  a1.y = a1.y*sc + p*c1.y;
        a1.z = a1.z*sc + p*c1.z;  a1.w = a1.w*sc + p*c1.w;
        a2.x = a2.x*sc + p*c2.x;  a2.y = a2.y*sc + p*c2.y;
        a2.z = a2.z*sc + p*c2.z;  a2.w = a2.w*sc + p*c2.w;
        a3.x = a3.x*sc + p*c3.x;  a3.y = a3.y*sc + p*c3.y;
        a3.z = a3.z*sc + p*c3.z;  a3.w = a3.w*sc + p*c3.w;
        l = l*sc + p;
        m = mn;

        c0 = n0; c1 = n1; c2 = n2; c3 = n3;
    }

    float4* gp = reinterpret_cast<float4*>(g_partial + (size_t)blockIdx.x * HIDDEN);
    gp[tid]       = a0;
    gp[tid + 256] = a1;
    gp[tid + 512] = a2;
    gp[tid + 768] = a3;
    if (tid == 0) { g_m[blockIdx.x] = m; g_l[blockIdx.x] = l; }
}

// ---- Pass 2: combine partials -> out; energies -> attn --------------------
// grid = 16 (out cols) + 32 (attn rows) = 48 blocks, 256 threads.
__global__ __launch_bounds__(256) void combine(
    float* __restrict__ out, float* __restrict__ attn)
{
    __shared__ float red[8];
    __shared__ float wsh[NBLK];
    __shared__ float sM, sZ;

    const int tid  = threadIdx.x;
    const int wid  = tid >> 5;
    const int lane = tid & 31;

    // global max M over 256 block maxima
    float mv = g_m[tid];
    #pragma unroll
    for (int off = 16; off > 0; off >>= 1)
        mv = fmaxf(mv, __shfl_xor_sync(0xFFFFFFFFu, mv, off));
    if (lane == 0) red[wid] = mv;
    __syncthreads();
    if (tid == 0) {
        float v = red[0];
        #pragma unroll
        for (int i = 1; i < 8; ++i) v = fmaxf(v, red[i]);
        sM = v;
    }
    __syncthreads();
    float M = sM;

    // per-block weights + global Z
    float w = __expf(g_m[tid] - M);
    wsh[tid] = w;
    float zt = g_l[tid] * w;
    #pragma unroll
    for (int off = 16; off > 0; off >>= 1)
        zt += __shfl_xor_sync(0xFFFFFFFFu, zt, off);
    if (lane == 0) red[wid] = zt;
    __syncthreads();
    if (tid == 0) {
        float v = red[0];
        #pragma unroll
        for (int i = 1; i < 8; ++i) v += red[i];
        sZ = v;
    }
    __syncthreads();
    float invZ = 1.0f / sZ;

    if (blockIdx.x < 16) {
        const int col = blockIdx.x * 256 + tid;
        float acc = 0.f;
        #pragma unroll 8
        for (int b = 0; b < NBLK; ++b)
            acc += g_partial[(size_t)b * HIDDEN + col] * wsh[b];
        out[col] = acc * invZ;
    } else {
        const int i = (blockIdx.x - 16) * 256 + tid;
        attn[i] = __expf(g_energies[i] - M) * invZ;
    }
}

extern "C" void kernel_launch(void* const* d_in, const int* in_sizes, int n_in,
                              void* d_out, int out_size)
{
    const float* hidden = (const float*)d_in[0];
    const float* enc    = (const float*)d_in[1];
    float* out  = (float*)d_out;
    float* attn = (float*)d_out + HIDDEN;

    pass1<<<NBLK, 256>>>(enc, hidden);
    combine<<<16 + SEQ_LEN / 256, 256>>>(out, attn);
}

// round 6
// speedup vs baseline: 1.4642x; 1.4642x over previous
#include <cuda_runtime.h>

// hidden [4096] f32, encoder_outputs [8192,1,4096] f32
// energies = enc @ hidden -> softmax -> output = enc^T @ attn
// d_out: [0:4096) = output, [4096:12288) = attn
//
// Single-pass over enc (read once) with online softmax; partials combined by
// a wide atomic-reduction grid.

#define SEQ_LEN 8192
#define HIDDEN  4096
#define H4      (HIDDEN / 4)
#define NBLK    512
#define ROWS_A  (SEQ_LEN / NBLK)    // 16 rows per block
#define BCHUNK  32                  // partials reduced per combine block
#define NBCH    (NBLK / BCHUNK)     // 16

__device__ float g_energies[SEQ_LEN];
__device__ float g_partial[NBLK * HIDDEN];
__device__ float g_m[NBLK];
__device__ float g_l[NBLK];
__device__ float g_w[NBLK];         // exp(m_b - M) / Z
__device__ float g_stats[2];        // {M, invZ}

// ---- Pass 1: fused energies + online-softmax accumulation; zeroes out ----
__global__ __launch_bounds__(256) void pass1(
    const float* __restrict__ enc, const float* __restrict__ hidden,
    float* __restrict__ out)
{
    const int tid  = threadIdx.x;
    const int wid  = tid >> 5;
    const int lane = tid & 31;
    const int r0   = blockIdx.x * ROWS_A;

    if (blockIdx.x < 16) out[blockIdx.x * 256 + tid] = 0.f;

    __shared__ float sm[2][8];

    const float4* h4 = reinterpret_cast<const float4*>(hidden);
    float4 hv0 = h4[tid];
    float4 hv1 = h4[tid + 256];
    float4 hv2 = h4[tid + 512];
    float4 hv3 = h4[tid + 768];

    const float4* base = reinterpret_cast<const float4*>(enc + (size_t)r0 * HIDDEN);

    float4 c0 = base[tid];
    float4 c1 = base[tid + 256];
    float4 c2 = base[tid + 512];
    float4 c3 = base[tid + 768];

    float4 a0 = make_float4(0.f,0.f,0.f,0.f);
    float4 a1 = a0, a2 = a0, a3 = a0;
    float m = -3.4e38f;
    float l = 0.f;

    #pragma unroll 1
    for (int s = 0; s < ROWS_A; ++s) {
        int sn = (s + 1 < ROWS_A) ? s + 1 : s;
        const float4* nb = base + (size_t)sn * H4;
        float4 n0 = nb[tid];
        float4 n1 = nb[tid + 256];
        float4 n2 = nb[tid + 512];
        float4 n3 = nb[tid + 768];

        float part = c0.x*hv0.x + c0.y*hv0.y + c0.z*hv0.z + c0.w*hv0.w
                   + c1.x*hv1.x + c1.y*hv1.y + c1.z*hv1.z + c1.w*hv1.w
                   + c2.x*hv2.x + c2.y*hv2.y + c2.z*hv2.z + c2.w*hv2.w
                   + c3.x*hv3.x + c3.y*hv3.y + c3.z*hv3.z + c3.w*hv3.w;
        #pragma unroll
        for (int off = 16; off > 0; off >>= 1)
            part += __shfl_down_sync(0xFFFFFFFFu, part, off);
        if (lane == 0) sm[s & 1][wid] = part;
        __syncthreads();
        float e = sm[s & 1][0] + sm[s & 1][1] + sm[s & 1][2] + sm[s & 1][3]
                + sm[s & 1][4] + sm[s & 1][5] + sm[s & 1][6] + sm[s & 1][7];
        if (tid == 0) g_energies[r0 + s] = e;

        float mn = fmaxf(m, e);
        float sc = __expf(m - mn);
        float p  = __expf(e - mn);
        a0.x = a0.x*sc + p*c0.x;  a0.y = a0.y*sc + p*c0.y;
        a0.z = a0.z*sc + p*c0.z;  a0.w = a0.w*sc + p*c0.w;
        a1.x = a1.x*sc + p*c1.x;  a1.y = a1.y*sc + p*c1.y;
        a1.z = a1.z*sc + p*c1.z;  a1.w = a1.w*sc + p*c1.w;
        a2.x = a2.x*sc + p*c2.x;  a2.y = a2.y*sc + p*c2.y;
        a2.z = a2.z*sc + p*c2.z;  a2.w = a2.w*sc + p*c2.w;
        a3.x = a3.x*sc + p*c3.x;  a3.y = a3.y*sc + p*c3.y;
        a3.z = a3.z*sc + p*c3.z;  a3.w = a3.w*sc + p*c3.w;
        l = l*sc + p;
        m = mn;

        c0 = n0; c1 = n1; c2 = n2; c3 = n3;
    }

    float4* gp = reinterpret_cast<float4*>(g_partial + (size_t)blockIdx.x * HIDDEN);
    gp[tid]       = a0;
    gp[tid + 256] = a1;
    gp[tid + 512] = a2;
    gp[tid + 768] = a3;
    if (tid == 0) { g_m[blockIdx.x] = m; g_l[blockIdx.x] = l; }
}

// ---- Finalize: M, Z, per-block weights (1 block, 512 threads) ------------
__global__ __launch_bounds__(NBLK) void finalize_stats()
{
    __shared__ float red[16];
    __shared__ float sM, sZ;
    const int tid  = threadIdx.x;
    const int wid  = tid >> 5;
    const int lane = tid & 31;

    float mb = g_m[tid];
    float mv = mb;
    #pragma unroll
    for (int off = 16; off > 0; off >>= 1)
        mv = fmaxf(mv, __shfl_xor_sync(0xFFFFFFFFu, mv, off));
    if (lane == 0) red[wid] = mv;
    __syncthreads();
    if (tid == 0) {
        float v = red[0];
        #pragma unroll
        for (int i = 1; i < 16; ++i) v = fmaxf(v, red[i]);
        sM = v;
    }
    __syncthreads();
    float M = sM;

    float w  = __expf(mb - M);
    float zt = g_l[tid] * w;
    #pragma unroll
    for (int off = 16; off > 0; off >>= 1)
        zt += __shfl_xor_sync(0xFFFFFFFFu, zt, off);
    if (lane == 0) red[wid] = zt;
    __syncthreads();
    if (tid == 0) {
        float v = red[0];
        #pragma unroll
        for (int i = 1; i < 16; ++i) v += red[i];
        sZ = v;
    }
    __syncthreads();
    float invZ = 1.0f / sZ;

    g_w[tid] = w * invZ;
    if (tid == 0) { g_stats[0] = M; g_stats[1] = invZ; }
}

// ---- Combine: blocks [0,256) accumulate out; [256,288) write attn --------
__global__ __launch_bounds__(256) void combine(
    float* __restrict__ out, float* __restrict__ attn)
{
    const int tid = threadIdx.x;
    const int gid = blockIdx.x;

    if (gid < NBCH * 16) {
        const int col = (gid & 15) * 256 + tid;
        const int b0  = (gid >> 4) * BCHUNK;
        float acc = 0.f;
        #pragma unroll 8
        for (int b = b0; b < b0 + BCHUNK; ++b)
            acc += g_partial[(size_t)b * HIDDEN + col] * g_w[b];
        atomicAdd(&out[col], acc);
    } else {
        const float M    = g_stats[0];
        const float invZ = g_stats[1];
        const int i = (gid - NBCH * 16) * 256 + tid;
        attn[i] = __expf(g_energies[i] - M) * invZ;
    }
}

extern "C" void kernel_launch(void* const* d_in, const int* in_sizes, int n_in,
                              void* d_out, int out_size)
{
    const float* hidden = (const float*)d_in[0];
    const float* enc    = (const float*)d_in[1];
    float* out  = (float*)d_out;
    float* attn = (float*)d_out + HIDDEN;

    pass1<<<NBLK, 256>>>(enc, hidden, out);
    finalize_stats<<<1, NBLK>>>();
    combine<<<NBCH * 16 + SEQ_LEN / 256, 256>>>(out, attn);
}